// round 1
// baseline (speedup 1.0000x reference)
#include <cuda_runtime.h>
#include <cuda_bf16.h>
#include <math.h>

// ---------------- problem constants ----------------
#define BB 32
#define HH 56
#define WW 56
#define CC 192
#define WS 7
#define SHIFT 3
#define HEADS 6
#define HID 768
#define NN 49          // tokens per window
#define NWIN 64        // windows per image
#define HD 32          // head dim
#define TOK (BB*HH*WW) // 100352 rows

// ---------------- scratch (static device globals; no allocation) ----------------
__device__ float g_hwin[(size_t)TOK * CC];      // LN1 output in window layout; reused for LN2 output
__device__ float g_qkv [(size_t)TOK * 3 * CC];  // qkv projections (window layout)
__device__ float g_obuf[(size_t)TOK * CC];      // attention output (window layout)
__device__ float g_proj[(size_t)TOK * CC];      // proj output (window layout)
__device__ float g_x1  [(size_t)TOK * CC];      // x + attn branch (image layout)
__device__ float g_m1  [(size_t)TOK * HID];     // gelu(fc1) output

// ---------------- LayerNorm (1 warp per row), optional shift+window gather ----------------
template<bool WINDOW_MAP>
__global__ void ln_kernel(const float* __restrict__ x,
                          const float* __restrict__ w,
                          const float* __restrict__ b,
                          float* __restrict__ out)
{
    int row  = blockIdx.x * (blockDim.x >> 5) + (threadIdx.x >> 5);
    int lane = threadIdx.x & 31;
    if (row >= TOK) return;

    int src;
    if (WINDOW_MAP) {
        int widx = row / NN;        // global window index
        int n    = row % NN;
        int bb   = widx / NWIN;
        int wi   = widx % NWIN;
        int wh   = wi / (WW / WS);
        int ww   = wi % (WW / WS);
        int hs   = wh * WS + n / WS;
        int ws   = ww * WS + n % WS;
        int h0   = (hs + SHIFT) % HH;   // roll(-SHIFT): shifted[i] = orig[(i+SHIFT)%H]
        int w0   = (ws + SHIFT) % WW;
        src = (bb * HH + h0) * WW + w0;
    } else {
        src = row;
    }

    const float* xr = x + (size_t)src * CC;
    float v[6];
    float s = 0.f;
#pragma unroll
    for (int i = 0; i < 6; i++) { v[i] = xr[lane + 32 * i]; s += v[i]; }
#pragma unroll
    for (int o = 16; o; o >>= 1) s += __shfl_xor_sync(0xffffffffu, s, o);
    float mu = s * (1.0f / CC);
    float vs = 0.f;
#pragma unroll
    for (int i = 0; i < 6; i++) { float d = v[i] - mu; vs += d * d; }
#pragma unroll
    for (int o = 16; o; o >>= 1) vs += __shfl_xor_sync(0xffffffffu, vs, o);
    float rstd = rsqrtf(vs * (1.0f / CC) + 1e-5f);

    float* orow = out + (size_t)row * CC;
#pragma unroll
    for (int i = 0; i < 6; i++) {
        int c = lane + 32 * i;
        orow[c] = (v[i] - mu) * rstd * w[c] + b[c];
    }
}

// ---------------- generic tiled SGEMM: C = act(A@W + bias) (+ residual) ----------------
// BM=BN=64, BK=16, 256 threads, 4x4 microtile. M%64==0, N%64==0, K%16==0 guaranteed.
__global__ __launch_bounds__(256)
void gemm_kernel(const float* __restrict__ A, const float* __restrict__ Wt,
                 const float* __restrict__ bias, const float* __restrict__ residual,
                 float* __restrict__ Cc, int M, int Nc, int K, int act)
{
    __shared__ __align__(16) float As[16][64];
    __shared__ __align__(16) float Bs[16][64];

    int tid = threadIdx.x;
    int tx = tid & 15;          // 0..15 (col group)
    int ty = tid >> 4;          // 0..15 (row group)
    int m0 = blockIdx.y * 64;
    int n0 = blockIdx.x * 64;

    // load indices
    int am = tid >> 2;            // 0..63
    int ak = (tid & 3) * 4;       // 0,4,8,12
    int bk = tid >> 4;            // 0..15
    int bn = (tid & 15) * 4;      // 0..60

    float acc[4][4] = {};

    for (int k0 = 0; k0 < K; k0 += 16) {
        float4 av = *(const float4*)(A  + (size_t)(m0 + am) * K  + k0 + ak);
        float4 bv = *(const float4*)(Wt + (size_t)(k0 + bk) * Nc + n0 + bn);
        As[ak + 0][am] = av.x;
        As[ak + 1][am] = av.y;
        As[ak + 2][am] = av.z;
        As[ak + 3][am] = av.w;
        *(float4*)&Bs[bk][bn] = bv;
        __syncthreads();
#pragma unroll
        for (int kk = 0; kk < 16; kk++) {
            float4 a4 = *(const float4*)&As[kk][ty * 4];
            float4 b4 = *(const float4*)&Bs[kk][tx * 4];
            float a[4] = {a4.x, a4.y, a4.z, a4.w};
            float bb2[4] = {b4.x, b4.y, b4.z, b4.w};
#pragma unroll
            for (int i = 0; i < 4; i++)
#pragma unroll
                for (int j = 0; j < 4; j++)
                    acc[i][j] = fmaf(a[i], bb2[j], acc[i][j]);
        }
        __syncthreads();
    }

#pragma unroll
    for (int i = 0; i < 4; i++) {
        int row = m0 + ty * 4 + i;
#pragma unroll
        for (int j = 0; j < 4; j++) {
            int col = n0 + tx * 4 + j;
            float c = acc[i][j] + bias[col];
            if (act == 1) {
                // exact GELU
                c = 0.5f * c * (1.0f + erff(c * 0.70710678118654752f));
            }
            size_t idx = (size_t)row * Nc + col;
            if (residual) c += residual[idx];
            Cc[idx] = c;
        }
    }
}

// ---------------- attention: one block per (window, head) ----------------
__global__ __launch_bounds__(128)
void attn_kernel(const float* __restrict__ qkv,
                 const float* __restrict__ bias_table,
                 const int*   __restrict__ rel_index,
                 const float* __restrict__ mask,
                 float* __restrict__ obuf)
{
    int blk  = blockIdx.x;
    int head = blk % HEADS;
    int widx = blk / HEADS;
    int wi   = widx % NWIN;

    __shared__ float q[NN][HD], k[NN][HD], v[NN][HD];
    __shared__ float s[NN][NN + 1];

    int tid = threadIdx.x;
    const float scale = 0.17677669529663687f; // 32^-0.5

    // load q,k,v for this head
    for (int idx = tid; idx < NN * HD; idx += 128) {
        int i = idx >> 5;          // token
        int d = idx & 31;          // dim
        size_t base = (size_t)(widx * NN + i) * (3 * CC);
        q[i][d] = qkv[base + head * HD + d] * scale;
        k[i][d] = qkv[base + CC + head * HD + d];
        v[i][d] = qkv[base + 2 * CC + head * HD + d];
    }
    __syncthreads();

    // scores + bias + mask
    const float* mrow = mask + (size_t)wi * NN * NN;
    for (int idx = tid; idx < NN * NN; idx += 128) {
        int i = idx / NN, j = idx % NN;
        float acc = 0.f;
#pragma unroll
        for (int d = 0; d < HD; d++) acc = fmaf(q[i][d], k[j][d], acc);
        acc += bias_table[rel_index[i * NN + j] * HEADS + head];
        acc += mrow[i * NN + j];
        s[i][j] = acc;
    }
    __syncthreads();

    // softmax: warp per row (4 warps round-robin over 49 rows)
    int warp = tid >> 5, lane = tid & 31;
    for (int i = warp; i < NN; i += 4) {
        float x1 = s[i][lane];
        float x2 = (lane + 32 < NN) ? s[i][lane + 32] : -1e30f;
        float m = fmaxf(x1, x2);
#pragma unroll
        for (int o = 16; o; o >>= 1) m = fmaxf(m, __shfl_xor_sync(0xffffffffu, m, o));
        float e1 = __expf(x1 - m);
        float e2 = (lane + 32 < NN) ? __expf(x2 - m) : 0.f;
        float sum = e1 + e2;
#pragma unroll
        for (int o = 16; o; o >>= 1) sum += __shfl_xor_sync(0xffffffffu, sum, o);
        float inv = 1.0f / sum;
        s[i][lane] = e1 * inv;
        if (lane + 32 < NN) s[i][lane + 32] = e2 * inv;
    }
    __syncthreads();

    // O = S @ V
    for (int idx = tid; idx < NN * HD; idx += 128) {
        int i = idx >> 5;
        int d = idx & 31;
        float acc = 0.f;
#pragma unroll
        for (int j = 0; j < NN; j++) acc = fmaf(s[i][j], v[j][d], acc);
        obuf[(size_t)(widx * NN + i) * CC + head * HD + d] = acc;
    }
}

// ---------------- window reverse + unshift + residual add (float4) ----------------
__global__ void add_reverse_kernel(const float* __restrict__ x,
                                   const float* __restrict__ proj,
                                   float* __restrict__ x1)
{
    size_t gid = (size_t)blockIdx.x * blockDim.x + threadIdx.x;
    size_t idx4 = gid * 4;
    if (idx4 >= (size_t)TOK * CC) return;
    int row = (int)(idx4 / CC);
    int c   = (int)(idx4 % CC);
    int bimg = row / (HH * WW);
    int hw   = row % (HH * WW);
    int h    = hw / WW;
    int w    = hw % WW;
    int hs = (h - SHIFT + HH) % HH;   // roll(+SHIFT): out[i] = in[(i-SHIFT)%H]
    int ws = (w - SHIFT + WW) % WW;
    int wh = hs / WS, r = hs % WS;
    int ww2 = ws / WS, cc2 = ws % WS;
    int srcrow = (bimg * NWIN + wh * (WW / WS) + ww2) * NN + r * WS + cc2;
    float4 xv = *(const float4*)(x + idx4);
    float4 pv = *(const float4*)(proj + (size_t)srcrow * CC + c);
    float4 o;
    o.x = xv.x + pv.x; o.y = xv.y + pv.y; o.z = xv.z + pv.z; o.w = xv.w + pv.w;
    *(float4*)(x1 + idx4) = o;
}

// ---------------- launch ----------------
extern "C" void kernel_launch(void* const* d_in, const int* in_sizes, int n_in,
                              void* d_out, int out_size)
{
    const float* x          = (const float*)d_in[0];
    const float* norm1_w    = (const float*)d_in[1];
    const float* norm1_b    = (const float*)d_in[2];
    const float* qkv_w      = (const float*)d_in[3];
    const float* qkv_b      = (const float*)d_in[4];
    const float* bias_table = (const float*)d_in[5];
    const float* proj_w     = (const float*)d_in[6];
    const float* proj_b     = (const float*)d_in[7];
    const float* norm2_w    = (const float*)d_in[8];
    const float* norm2_b    = (const float*)d_in[9];
    const float* fc1_w      = (const float*)d_in[10];
    const float* fc1_b      = (const float*)d_in[11];
    const float* fc2_w      = (const float*)d_in[12];
    const float* fc2_b      = (const float*)d_in[13];
    const float* attn_mask  = (const float*)d_in[14];
    const int*   rel_index  = (const int*)  d_in[15];
    float* out = (float*)d_out;

    float *hwin, *qkv, *obuf, *proj, *x1, *m1;
    cudaGetSymbolAddress((void**)&hwin, g_hwin);
    cudaGetSymbolAddress((void**)&qkv,  g_qkv);
    cudaGetSymbolAddress((void**)&obuf, g_obuf);
    cudaGetSymbolAddress((void**)&proj, g_proj);
    cudaGetSymbolAddress((void**)&x1,   g_x1);
    cudaGetSymbolAddress((void**)&m1,   g_m1);

    // 1. LN1 + shift + window partition
    ln_kernel<true><<<TOK / 8, 256>>>(x, norm1_w, norm1_b, hwin);

    // 2. QKV gemm: [TOK,192] @ [192,576]
    gemm_kernel<<<dim3(576 / 64, TOK / 64), 256>>>(hwin, qkv_w, qkv_b, nullptr, qkv,
                                                   TOK, 576, CC, 0);

    // 3. attention per (window, head)
    attn_kernel<<<(TOK / NN) * HEADS, 128>>>(qkv, bias_table, rel_index, attn_mask, obuf);

    // 4. proj gemm: [TOK,192] @ [192,192]
    gemm_kernel<<<dim3(192 / 64, TOK / 64), 256>>>(obuf, proj_w, proj_b, nullptr, proj,
                                                   TOK, CC, CC, 0);

    // 5. window reverse + unshift + residual
    {
        size_t nvec = (size_t)TOK * CC / 4;
        add_reverse_kernel<<<(unsigned)((nvec + 255) / 256), 256>>>(x, proj, x1);
    }

    // 6. LN2 (reuse hwin)
    ln_kernel<false><<<TOK / 8, 256>>>(x1, norm2_w, norm2_b, hwin);

    // 7. fc1 + exact GELU: [TOK,192] @ [192,768]
    gemm_kernel<<<dim3(HID / 64, TOK / 64), 256>>>(hwin, fc1_w, fc1_b, nullptr, m1,
                                                   TOK, HID, CC, 1);

    // 8. fc2 + residual -> out: [TOK,768] @ [768,192]
    gemm_kernel<<<dim3(192 / 64, TOK / 64), 256>>>(m1, fc2_w, fc2_b, x1, out,
                                                   TOK, CC, HID, 0);
}

// round 6
// speedup vs baseline: 1.8909x; 1.8909x over previous
#include <cuda_runtime.h>
#include <cuda_bf16.h>
#include <stdint.h>
#include <math.h>

// ---------------- problem constants ----------------
#define BB 32
#define HH 56
#define WW 56
#define CC 192
#define WS 7
#define SHIFT 3
#define HEADS 6
#define HID 768
#define NN 49          // tokens per window
#define NWIN 64        // windows per image
#define HD 32          // head dim
#define TOK (BB*HH*WW) // 100352 rows

// ---------------- scratch ----------------
__device__ float g_hwin[(size_t)TOK * CC];
__device__ float g_qkv [(size_t)TOK * 3 * CC];
__device__ float g_obuf[(size_t)TOK * CC];
__device__ float g_proj[(size_t)TOK * CC];
__device__ float g_x1  [(size_t)TOK * CC];
__device__ float g_m1  [(size_t)TOK * HID];

__device__ __forceinline__ unsigned int f2tf(float f) {
    unsigned int u;
    asm("cvt.rna.tf32.f32 %0, %1;" : "=r"(u) : "f"(f));
    return u;
}

// ---------------- LayerNorm (1 warp/row), optional shift+window gather ----------------
template<bool WINDOW_MAP>
__global__ void ln_kernel(const float* __restrict__ x,
                          const float* __restrict__ w,
                          const float* __restrict__ b,
                          float* __restrict__ out)
{
    int row  = blockIdx.x * (blockDim.x >> 5) + (threadIdx.x >> 5);
    int lane = threadIdx.x & 31;
    if (row >= TOK) return;

    int src;
    if (WINDOW_MAP) {
        int widx = row / NN;
        int n    = row % NN;
        int bb   = widx / NWIN;
        int wi   = widx % NWIN;
        int wh   = wi / (WW / WS);
        int ww   = wi % (WW / WS);
        int hs   = wh * WS + n / WS;
        int ws   = ww * WS + n % WS;
        int h0   = (hs + SHIFT) % HH;
        int w0   = (ws + SHIFT) % WW;
        src = (bb * HH + h0) * WW + w0;
    } else {
        src = row;
    }

    const float* xr = x + (size_t)src * CC;
    float v[6];
    float s = 0.f;
#pragma unroll
    for (int i = 0; i < 6; i++) { v[i] = xr[lane + 32 * i]; s += v[i]; }
#pragma unroll
    for (int o = 16; o; o >>= 1) s += __shfl_xor_sync(0xffffffffu, s, o);
    float mu = s * (1.0f / CC);
    float vs = 0.f;
#pragma unroll
    for (int i = 0; i < 6; i++) { float d = v[i] - mu; vs += d * d; }
#pragma unroll
    for (int o = 16; o; o >>= 1) vs += __shfl_xor_sync(0xffffffffu, vs, o);
    float rstd = rsqrtf(vs * (1.0f / CC) + 1e-5f);

    float* orow = out + (size_t)row * CC;
#pragma unroll
    for (int i = 0; i < 6; i++) {
        int c = lane + 32 * i;
        orow[c] = (v[i] - mu) * rstd * w[c] + b[c];
    }
}

// ---------------- tensor-core TF32 GEMM: C = act(A@W + bias) (+ residual) ----------------
// BM=128, BN=64, BK=32. 256 threads = 8 warps (4m x 2n), warp tile 32x32.
// mma.sync.m16n8k8.tf32. M%128==0, N%64==0, K%32==0.
__global__ __launch_bounds__(256)
void gemm_tc(const float* __restrict__ A, const float* __restrict__ Wt,
             const float* __restrict__ bias, const float* __restrict__ residual,
             float* __restrict__ Cc, int M, int Nc, int K, int act)
{
    __shared__ unsigned int As[32][136];  // [k][m], stride%32==8 -> frag LDS conflict-free
    __shared__ unsigned int Bs[32][72];   // [k][n], stride%32==8

    int tid  = threadIdx.x;
    int lane = tid & 31;
    int warp = tid >> 5;
    int m0 = blockIdx.y * 128;
    int n0 = blockIdx.x * 64;
    int g = lane >> 2;   // groupID
    int q = lane & 3;    // thread-in-group
    int wm = (warp >> 1) * 32;
    int wn = (warp & 1) * 32;

    float acc[2][4][4] = {};

    for (int k0 = 0; k0 < K; k0 += 32) {
        // --- A tile: warp w loads k-chunk w (4 floats), rows = lane (+32r) ---
        {
            const float* ap = A + (size_t)(m0 + lane) * K + k0 + warp * 4;
#pragma unroll
            for (int r = 0; r < 4; r++) {
                float4 v = *(const float4*)(ap + (size_t)(32 * r) * K);
                int mm = lane + 32 * r;
                As[warp * 4 + 0][mm] = f2tf(v.x);
                As[warp * 4 + 1][mm] = f2tf(v.y);
                As[warp * 4 + 2][mm] = f2tf(v.z);
                As[warp * 4 + 3][mm] = f2tf(v.w);
            }
        }
        // --- B tile: 32x64, coalesced ---
#pragma unroll
        for (int it = 0; it < 2; it++) {
            int idx = tid + it * 256;
            int kb = idx >> 4;
            int nf = idx & 15;
            float4 v = *(const float4*)(Wt + (size_t)(k0 + kb) * Nc + n0 + nf * 4);
            Bs[kb][nf * 4 + 0] = f2tf(v.x);
            Bs[kb][nf * 4 + 1] = f2tf(v.y);
            Bs[kb][nf * 4 + 2] = f2tf(v.z);
            Bs[kb][nf * 4 + 3] = f2tf(v.w);
        }
        __syncthreads();

#pragma unroll
        for (int ks = 0; ks < 4; ks++) {
            int kk = ks * 8;
            unsigned int a[2][4], b[4][2];
#pragma unroll
            for (int mi = 0; mi < 2; mi++) {
                int mm = wm + mi * 16 + g;
                a[mi][0] = As[kk + q][mm];
                a[mi][1] = As[kk + q][mm + 8];
                a[mi][2] = As[kk + q + 4][mm];
                a[mi][3] = As[kk + q + 4][mm + 8];
            }
#pragma unroll
            for (int ni = 0; ni < 4; ni++) {
                int nn = wn + ni * 8 + g;
                b[ni][0] = Bs[kk + q][nn];
                b[ni][1] = Bs[kk + q + 4][nn];
            }
#pragma unroll
            for (int mi = 0; mi < 2; mi++)
#pragma unroll
                for (int ni = 0; ni < 4; ni++) {
                    asm("mma.sync.aligned.m16n8k8.row.col.f32.tf32.tf32.f32 "
                        "{%0,%1,%2,%3}, {%4,%5,%6,%7}, {%8,%9}, {%0,%1,%2,%3};"
                        : "+f"(acc[mi][ni][0]), "+f"(acc[mi][ni][1]),
                          "+f"(acc[mi][ni][2]), "+f"(acc[mi][ni][3])
                        : "r"(a[mi][0]), "r"(a[mi][1]), "r"(a[mi][2]), "r"(a[mi][3]),
                          "r"(b[ni][0]), "r"(b[ni][1]));
                }
        }
        __syncthreads();
    }

    // ---- epilogue ----
#pragma unroll
    for (int mi = 0; mi < 2; mi++) {
        int row0 = m0 + wm + mi * 16 + g;
#pragma unroll
        for (int ni = 0; ni < 4; ni++) {
            int col = n0 + wn + ni * 8 + 2 * q;
#pragma unroll
            for (int h = 0; h < 2; h++) {           // h=0 -> rows g / c0c1, h=1 -> rows g+8 / c2c3
                int row = row0 + h * 8;
                float c0 = acc[mi][ni][2 * h + 0] + bias[col];
                float c1 = acc[mi][ni][2 * h + 1] + bias[col + 1];
                if (act == 1) {
                    c0 = 0.5f * c0 * (1.0f + erff(c0 * 0.70710678118654752f));
                    c1 = 0.5f * c1 * (1.0f + erff(c1 * 0.70710678118654752f));
                }
                size_t idx = (size_t)row * Nc + col;
                if (residual) { c0 += residual[idx]; c1 += residual[idx + 1]; }
                Cc[idx] = c0;
                Cc[idx + 1] = c1;
            }
        }
    }
}

// ---------------- attention: one block per (window, head), conflict-free smem ----------------
__global__ __launch_bounds__(128)
void attn_kernel(const float* __restrict__ qkv,
                 const float* __restrict__ bias_table,
                 const int*   __restrict__ rel_index,
                 const float* __restrict__ mask,
                 float* __restrict__ obuf)
{
    int blk  = blockIdx.x;
    int head = blk % HEADS;
    int widx = blk / HEADS;
    int wi   = widx % NWIN;

    __shared__ float q[NN][HD + 1], k[NN][HD + 1], v[NN][HD + 1];
    __shared__ float s[NN][NN + 1];

    int tid = threadIdx.x;
    const float scale = 0.17677669529663687f;

    for (int idx = tid; idx < NN * HD; idx += 128) {
        int i = idx >> 5;
        int d = idx & 31;
        size_t base = (size_t)(widx * NN + i) * (3 * CC);
        q[i][d] = qkv[base + head * HD + d] * scale;
        k[i][d] = qkv[base + CC + head * HD + d];
        v[i][d] = qkv[base + 2 * CC + head * HD + d];
    }
    __syncthreads();

    // scores: unit = (i, jg) with 7-wide j register tile
    const float* mrow = mask + (size_t)wi * NN * NN;
    for (int u = tid; u < NN * 7; u += 128) {
        int i  = u / 7;
        int jg = u % 7;
        float a[7] = {};
#pragma unroll
        for (int d = 0; d < HD; d++) {
            float qd = q[i][d];
#pragma unroll
            for (int jj = 0; jj < 7; jj++)
                a[jj] = fmaf(qd, k[jg * 7 + jj][d], a[jj]);
        }
#pragma unroll
        for (int jj = 0; jj < 7; jj++) {
            int j = jg * 7 + jj;
            a[jj] += bias_table[rel_index[i * NN + j] * HEADS + head] + mrow[i * NN + j];
            s[i][j] = a[jj];
        }
    }
    __syncthreads();

    // softmax: warp per row
    int warp = tid >> 5, lane = tid & 31;
    for (int i = warp; i < NN; i += 4) {
        float x1 = s[i][lane];
        float x2 = (lane + 32 < NN) ? s[i][lane + 32] : -1e30f;
        float m = fmaxf(x1, x2);
#pragma unroll
        for (int o = 16; o; o >>= 1) m = fmaxf(m, __shfl_xor_sync(0xffffffffu, m, o));
        float e1 = __expf(x1 - m);
        float e2 = (lane + 32 < NN) ? __expf(x2 - m) : 0.f;
        float sum = e1 + e2;
#pragma unroll
        for (int o = 16; o; o >>= 1) sum += __shfl_xor_sync(0xffffffffu, sum, o);
        float inv = 1.0f / sum;
        s[i][lane] = e1 * inv;
        if (lane + 32 < NN) s[i][lane + 32] = e2 * inv;
    }
    __syncthreads();

    // O = S @ V : warp per row, lane = d (conflict-free)
    for (int r = warp; r < NN; r += 4) {
        float a0 = 0.f, a1 = 0.f;
#pragma unroll
        for (int j = 0; j < 48; j += 2) {
            a0 = fmaf(s[r][j],     v[j][lane],     a0);
            a1 = fmaf(s[r][j + 1], v[j + 1][lane], a1);
        }
        a0 = fmaf(s[r][48], v[48][lane], a0);
        obuf[(size_t)(widx * NN + r) * CC + head * HD + lane] = a0 + a1;
    }
}

// ---------------- window reverse + unshift + residual add ----------------
__global__ void add_reverse_kernel(const float* __restrict__ x,
                                   const float* __restrict__ proj,
                                   float* __restrict__ x1)
{
    size_t gid = (size_t)blockIdx.x * blockDim.x + threadIdx.x;
    size_t idx4 = gid * 4;
    if (idx4 >= (size_t)TOK * CC) return;
    int row = (int)(idx4 / CC);
    int c   = (int)(idx4 % CC);
    int bimg = row / (HH * WW);
    int hw   = row % (HH * WW);
    int h    = hw / WW;
    int w    = hw % WW;
    int hs = (h - SHIFT + HH) % HH;
    int ws = (w - SHIFT + WW) % WW;
    int wh = hs / WS, r = hs % WS;
    int ww2 = ws / WS, cc2 = ws % WS;
    int srcrow = (bimg * NWIN + wh * (WW / WS) + ww2) * NN + r * WS + cc2;
    float4 xv = *(const float4*)(x + idx4);
    float4 pv = *(const float4*)(proj + (size_t)srcrow * CC + c);
    float4 o;
    o.x = xv.x + pv.x; o.y = xv.y + pv.y; o.z = xv.z + pv.z; o.w = xv.w + pv.w;
    *(float4*)(x1 + idx4) = o;
}

// ---------------- launch ----------------
extern "C" void kernel_launch(void* const* d_in, const int* in_sizes, int n_in,
                              void* d_out, int out_size)
{
    const float* x          = (const float*)d_in[0];
    const float* norm1_w    = (const float*)d_in[1];
    const float* norm1_b    = (const float*)d_in[2];
    const float* qkv_w      = (const float*)d_in[3];
    const float* qkv_b      = (const float*)d_in[4];
    const float* bias_table = (const float*)d_in[5];
    const float* proj_w     = (const float*)d_in[6];
    const float* proj_b     = (const float*)d_in[7];
    const float* norm2_w    = (const float*)d_in[8];
    const float* norm2_b    = (const float*)d_in[9];
    const float* fc1_w      = (const float*)d_in[10];
    const float* fc1_b      = (const float*)d_in[11];
    const float* fc2_w      = (const float*)d_in[12];
    const float* fc2_b      = (const float*)d_in[13];
    const float* attn_mask  = (const float*)d_in[14];
    const int*   rel_index  = (const int*)  d_in[15];
    float* out = (float*)d_out;

    float *hwin, *qkv, *obuf, *proj, *x1, *m1;
    cudaGetSymbolAddress((void**)&hwin, g_hwin);
    cudaGetSymbolAddress((void**)&qkv,  g_qkv);
    cudaGetSymbolAddress((void**)&obuf, g_obuf);
    cudaGetSymbolAddress((void**)&proj, g_proj);
    cudaGetSymbolAddress((void**)&x1,   g_x1);
    cudaGetSymbolAddress((void**)&m1,   g_m1);

    // 1. LN1 + shift + window partition
    ln_kernel<true><<<TOK / 8, 256>>>(x, norm1_w, norm1_b, hwin);

    // 2. QKV gemm: [TOK,192] @ [192,576]
    gemm_tc<<<dim3(576 / 64, TOK / 128), 256>>>(hwin, qkv_w, qkv_b, nullptr, qkv,
                                                TOK, 576, CC, 0);

    // 3. attention
    attn_kernel<<<(TOK / NN) * HEADS, 128>>>(qkv, bias_table, rel_index, attn_mask, obuf);

    // 4. proj gemm
    gemm_tc<<<dim3(192 / 64, TOK / 128), 256>>>(obuf, proj_w, proj_b, nullptr, proj,
                                                TOK, CC, CC, 0);

    // 5. window reverse + unshift + residual
    {
        size_t nvec = (size_t)TOK * CC / 4;
        add_reverse_kernel<<<(unsigned)((nvec + 255) / 256), 256>>>(x, proj, x1);
    }

    // 6. LN2
    ln_kernel<false><<<TOK / 8, 256>>>(x1, norm2_w, norm2_b, hwin);

    // 7. fc1 + exact GELU
    gemm_tc<<<dim3(HID / 64, TOK / 128), 256>>>(hwin, fc1_w, fc1_b, nullptr, m1,
                                                TOK, HID, CC, 1);

    // 8. fc2 + residual -> out
    gemm_tc<<<dim3(192 / 64, TOK / 128), 256>>>(m1, fc2_w, fc2_b, x1, out,
                                                TOK, CC, HID, 0);
}

// round 7
// speedup vs baseline: 2.9079x; 1.5378x over previous
#include <cuda_runtime.h>
#include <cuda_bf16.h>
#include <stdint.h>
#include <math.h>

// ---------------- problem constants ----------------
#define BB 32
#define HH 56
#define WW 56
#define CC 192
#define WS 7
#define SHIFT 3
#define HEADS 6
#define HID 768
#define NN 49
#define NWIN 64
#define HD 32
#define TOK (BB*HH*WW)   // 100352

// weight scratch offsets (floats)
#define W_QKV 0
#define W_PROJ 110592
#define W_FC1 147456
#define W_FC2 294912
#define W_TOTAL 442368

// ---------------- scratch ----------------
__device__ float g_hwin[(size_t)TOK * CC];
__device__ float g_qkv [(size_t)TOK * 3 * CC];
__device__ float g_obuf[(size_t)TOK * CC];
__device__ float g_x1  [(size_t)TOK * CC];
__device__ float g_m1  [(size_t)TOK * HID];
__device__ float g_wr  [W_TOTAL];

__device__ __forceinline__ unsigned int f2tf(float f) {
    unsigned int u;
    asm("cvt.rna.tf32.f32 %0, %1;" : "=r"(u) : "f"(f));
    return u;
}
__device__ __forceinline__ float f2tf_f(float f) { return __uint_as_float(f2tf(f)); }

__device__ __forceinline__ void cp16(void* sp, const void* gp) {
    unsigned int sa = (unsigned int)__cvta_generic_to_shared(sp);
    asm volatile("cp.async.ca.shared.global [%0], [%1], 16;" :: "r"(sa), "l"(gp));
}

// ---------------- weight pre-round (tf32 rna) ----------------
__global__ void round_w_kernel(const float* __restrict__ a, const float* __restrict__ b,
                               const float* __restrict__ c, const float* __restrict__ d,
                               float* __restrict__ o)
{
    int i = blockIdx.x * 256 + threadIdx.x;
    if (i >= W_TOTAL) return;
    float v;
    if (i < W_PROJ)       v = a[i - W_QKV];
    else if (i < W_FC1)   v = b[i - W_PROJ];
    else if (i < W_FC2)   v = c[i - W_FC1];
    else                  v = d[i - W_FC2];
    o[i] = f2tf_f(v);
}

// ---------------- LayerNorm (1 warp/row); output tf32-rounded ----------------
template<bool WINDOW_MAP>
__global__ void ln_kernel(const float* __restrict__ x,
                          const float* __restrict__ w,
                          const float* __restrict__ b,
                          float* __restrict__ out)
{
    int row  = blockIdx.x * (blockDim.x >> 5) + (threadIdx.x >> 5);
    int lane = threadIdx.x & 31;
    if (row >= TOK) return;

    int src;
    if (WINDOW_MAP) {
        int widx = row / NN;
        int n    = row % NN;
        int bb   = widx / NWIN;
        int wi   = widx % NWIN;
        int wh   = wi / (WW / WS);
        int ww   = wi % (WW / WS);
        int hs   = wh * WS + n / WS;
        int ws   = ww * WS + n % WS;
        int h0   = (hs + SHIFT) % HH;
        int w0   = (ws + SHIFT) % WW;
        src = (bb * HH + h0) * WW + w0;
    } else {
        src = row;
    }

    const float* xr = x + (size_t)src * CC;
    float v[6];
    float s = 0.f;
#pragma unroll
    for (int i = 0; i < 6; i++) { v[i] = xr[lane + 32 * i]; s += v[i]; }
#pragma unroll
    for (int o = 16; o; o >>= 1) s += __shfl_xor_sync(0xffffffffu, s, o);
    float mu = s * (1.0f / CC);
    float vs = 0.f;
#pragma unroll
    for (int i = 0; i < 6; i++) { float d = v[i] - mu; vs += d * d; }
#pragma unroll
    for (int o = 16; o; o >>= 1) vs += __shfl_xor_sync(0xffffffffu, vs, o);
    float rstd = rsqrtf(vs * (1.0f / CC) + 1e-5f);

    float* orow = out + (size_t)row * CC;
#pragma unroll
    for (int i = 0; i < 6; i++) {
        int c = lane + 32 * i;
        orow[c] = f2tf_f((v[i] - mu) * rstd * w[c] + b[c]);
    }
}

// ---------------- TF32 tensor-core GEMM, cp.async double-buffered ----------------
// BM=128, BN=64, BK=32. 128 threads = 4 warps (2m x 2n), warp tile 64x32.
// Inputs assumed pre-rounded to tf32 values (raw-bit feed).
// EPI: 0 = bias; 1 = bias+gelu+round; 2 = bias + gather(aux=x) + scatter window-reverse -> Cc;
//      3 = bias + residual(aux) -> Cc
#define ASZ (128*36)
#define BSZ (32*68)
#define GEMM_SMEM ((2*ASZ + 2*BSZ)*4)

template<int K, int EPI>
__global__ __launch_bounds__(128)
void gemm_tc2(const float* __restrict__ A, const float* __restrict__ Wt,
              const float* __restrict__ bias, const float* __restrict__ aux,
              float* __restrict__ Cc, int Nc)
{
    extern __shared__ float sm[];

    int tid  = threadIdx.x;
    int lane = tid & 31;
    int warp = tid >> 5;
    int g = lane >> 2;
    int q = lane & 3;
    int wm = (warp >> 1) * 64;
    int wn = (warp & 1) * 32;
    int m0 = blockIdx.y * 128;
    int n0 = blockIdx.x * 64;

    // per-thread cp.async indices
    int a_m  = tid >> 3;           // + j*16
    int a_kc = (tid & 7) * 4;
    int b_k  = tid >> 4;           // + j*8
    int b_nc = (tid & 15) * 4;

    const float* Ab = A + (size_t)m0 * K + a_kc;
    const float* Bb = Wt + n0 + b_nc;

    float acc[4][4][4] = {};
    constexpr int KT = K / 32;

#define ISSUE(kt, s) do {                                                   \
        float* as_ = sm + (s) * ASZ;                                        \
        float* bs_ = sm + 2 * ASZ + (s) * BSZ;                              \
        _Pragma("unroll")                                                   \
        for (int j = 0; j < 8; j++) {                                       \
            int m_ = a_m + j * 16;                                          \
            cp16(&as_[m_ * 36 + a_kc], Ab + (size_t)m_ * K + (kt) * 32);    \
        }                                                                   \
        _Pragma("unroll")                                                   \
        for (int j = 0; j < 4; j++) {                                       \
            int k_ = b_k + j * 8;                                           \
            cp16(&bs_[k_ * 68 + b_nc], Bb + (size_t)((kt) * 32 + k_) * Nc); \
        }                                                                   \
        asm volatile("cp.async.commit_group;");                             \
    } while (0)

    ISSUE(0, 0);
    for (int kt = 0; kt < KT; kt++) {
        if (kt + 1 < KT) { ISSUE(kt + 1, (kt + 1) & 1); }
        else             { asm volatile("cp.async.commit_group;"); }
        asm volatile("cp.async.wait_group 1;");
        __syncthreads();

        const float* as = sm + (kt & 1) * ASZ;
        const float* bs = sm + 2 * ASZ + (kt & 1) * BSZ;
#pragma unroll
        for (int ks = 0; ks < 4; ks++) {
            int kk = ks * 8;
            unsigned int a[4][4], b[4][2];
#pragma unroll
            for (int mi = 0; mi < 4; mi++) {
                int mm = wm + mi * 16 + g;
                a[mi][0] = __float_as_uint(as[mm * 36 + kk + q]);
                a[mi][1] = __float_as_uint(as[(mm + 8) * 36 + kk + q]);
                a[mi][2] = __float_as_uint(as[mm * 36 + kk + q + 4]);
                a[mi][3] = __float_as_uint(as[(mm + 8) * 36 + kk + q + 4]);
            }
#pragma unroll
            for (int ni = 0; ni < 4; ni++) {
                int nn = wn + ni * 8 + g;
                b[ni][0] = __float_as_uint(bs[(kk + q) * 68 + nn]);
                b[ni][1] = __float_as_uint(bs[(kk + q + 4) * 68 + nn]);
            }
#pragma unroll
            for (int mi = 0; mi < 4; mi++)
#pragma unroll
                for (int ni = 0; ni < 4; ni++) {
                    asm("mma.sync.aligned.m16n8k8.row.col.f32.tf32.tf32.f32 "
                        "{%0,%1,%2,%3}, {%4,%5,%6,%7}, {%8,%9}, {%0,%1,%2,%3};"
                        : "+f"(acc[mi][ni][0]), "+f"(acc[mi][ni][1]),
                          "+f"(acc[mi][ni][2]), "+f"(acc[mi][ni][3])
                        : "r"(a[mi][0]), "r"(a[mi][1]), "r"(a[mi][2]), "r"(a[mi][3]),
                          "r"(b[ni][0]), "r"(b[ni][1]));
                }
        }
        __syncthreads();
    }
#undef ISSUE

    // ---- epilogue ----
#pragma unroll
    for (int mi = 0; mi < 4; mi++) {
#pragma unroll
        for (int h = 0; h < 2; h++) {
            int row = m0 + wm + mi * 16 + g + h * 8;
            size_t base;
            if (EPI == 2) {
                int widx = row / NN;
                int n    = row % NN;
                int bimg = widx >> 6;
                int wi   = widx & 63;
                int hs = (wi >> 3) * WS + n / WS;
                int ws = (wi & 7) * WS + n % WS;
                int h2 = hs + SHIFT; if (h2 >= HH) h2 -= HH;
                int w2 = ws + SHIFT; if (w2 >= WW) w2 -= WW;
                base = (size_t)((bimg * HH + h2) * WW + w2) * CC;
            } else {
                base = (size_t)row * Nc;
            }
#pragma unroll
            for (int ni = 0; ni < 4; ni++) {
                int col = n0 + wn + ni * 8 + 2 * q;
                float c0 = acc[mi][ni][2 * h + 0] + bias[col];
                float c1 = acc[mi][ni][2 * h + 1] + bias[col + 1];
                if (EPI == 1) {
                    c0 = f2tf_f(0.5f * c0 * (1.0f + erff(c0 * 0.70710678118654752f)));
                    c1 = f2tf_f(0.5f * c1 * (1.0f + erff(c1 * 0.70710678118654752f)));
                }
                size_t idx = base + col;
                if (EPI == 2 || EPI == 3) {
                    float2 av = *(const float2*)(aux + idx);
                    c0 += av.x; c1 += av.y;
                }
                float2 o; o.x = c0; o.y = c1;
                *(float2*)(Cc + idx) = o;
            }
        }
    }
}

// ---------------- attention: block per (window, head); output tf32-rounded ----------------
__global__ __launch_bounds__(128)
void attn_kernel(const float* __restrict__ qkv,
                 const float* __restrict__ bias_table,
                 const int*   __restrict__ rel_index,
                 const float* __restrict__ mask,
                 float* __restrict__ obuf)
{
    int blk  = blockIdx.x;
    int head = blk % HEADS;
    int widx = blk / HEADS;
    int wi   = widx % NWIN;

    __shared__ float q[NN][HD + 1], k[NN][HD + 1], v[NN][HD + 1];
    __shared__ float s[NN][NN + 1];

    int tid = threadIdx.x;
    const float scale = 0.17677669529663687f;

    for (int idx = tid; idx < NN * HD; idx += 128) {
        int i = idx >> 5;
        int d = idx & 31;
        size_t base = (size_t)(widx * NN + i) * (3 * CC);
        q[i][d] = qkv[base + head * HD + d] * scale;
        k[i][d] = qkv[base + CC + head * HD + d];
        v[i][d] = qkv[base + 2 * CC + head * HD + d];
    }
    __syncthreads();

    const float* mrow = mask + (size_t)wi * NN * NN;
    for (int u = tid; u < NN * 7; u += 128) {
        int i  = u / 7;
        int jg = u % 7;
        float a[7] = {};
#pragma unroll
        for (int d = 0; d < HD; d++) {
            float qd = q[i][d];
#pragma unroll
            for (int jj = 0; jj < 7; jj++)
                a[jj] = fmaf(qd, k[jg * 7 + jj][d], a[jj]);
        }
#pragma unroll
        for (int jj = 0; jj < 7; jj++) {
            int j = jg * 7 + jj;
            a[jj] += bias_table[rel_index[i * NN + j] * HEADS + head] + mrow[i * NN + j];
            s[i][j] = a[jj];
        }
    }
    __syncthreads();

    int warp = tid >> 5, lane = tid & 31;
    for (int i = warp; i < NN; i += 4) {
        float x1 = s[i][lane];
        float x2 = (lane + 32 < NN) ? s[i][lane + 32] : -1e30f;
        float m = fmaxf(x1, x2);
#pragma unroll
        for (int o = 16; o; o >>= 1) m = fmaxf(m, __shfl_xor_sync(0xffffffffu, m, o));
        float e1 = __expf(x1 - m);
        float e2 = (lane + 32 < NN) ? __expf(x2 - m) : 0.f;
        float sum = e1 + e2;
#pragma unroll
        for (int o = 16; o; o >>= 1) sum += __shfl_xor_sync(0xffffffffu, sum, o);
        float inv = 1.0f / sum;
        s[i][lane] = e1 * inv;
        if (lane + 32 < NN) s[i][lane + 32] = e2 * inv;
    }
    __syncthreads();

    for (int r = warp; r < NN; r += 4) {
        float a0 = 0.f, a1 = 0.f;
#pragma unroll
        for (int j = 0; j < 48; j += 2) {
            a0 = fmaf(s[r][j],     v[j][lane],     a0);
            a1 = fmaf(s[r][j + 1], v[j + 1][lane], a1);
        }
        a0 = fmaf(s[r][48], v[48][lane], a0);
        obuf[(size_t)(widx * NN + r) * CC + head * HD + lane] = f2tf_f(a0 + a1);
    }
}

// ---------------- launch ----------------
extern "C" void kernel_launch(void* const* d_in, const int* in_sizes, int n_in,
                              void* d_out, int out_size)
{
    const float* x          = (const float*)d_in[0];
    const float* norm1_w    = (const float*)d_in[1];
    const float* norm1_b    = (const float*)d_in[2];
    const float* qkv_w      = (const float*)d_in[3];
    const float* qkv_b      = (const float*)d_in[4];
    const float* bias_table = (const float*)d_in[5];
    const float* proj_w     = (const float*)d_in[6];
    const float* proj_b     = (const float*)d_in[7];
    const float* norm2_w    = (const float*)d_in[8];
    const float* norm2_b    = (const float*)d_in[9];
    const float* fc1_w      = (const float*)d_in[10];
    const float* fc1_b      = (const float*)d_in[11];
    const float* fc2_w      = (const float*)d_in[12];
    const float* fc2_b      = (const float*)d_in[13];
    const float* attn_mask  = (const float*)d_in[14];
    const int*   rel_index  = (const int*)  d_in[15];
    float* out = (float*)d_out;

    float *hwin, *qkv, *obuf, *x1, *m1, *wr;
    cudaGetSymbolAddress((void**)&hwin, g_hwin);
    cudaGetSymbolAddress((void**)&qkv,  g_qkv);
    cudaGetSymbolAddress((void**)&obuf, g_obuf);
    cudaGetSymbolAddress((void**)&x1,   g_x1);
    cudaGetSymbolAddress((void**)&m1,   g_m1);
    cudaGetSymbolAddress((void**)&wr,   g_wr);

    cudaFuncSetAttribute(gemm_tc2<192,0>, cudaFuncAttributeMaxDynamicSharedMemorySize, GEMM_SMEM);
    cudaFuncSetAttribute(gemm_tc2<192,1>, cudaFuncAttributeMaxDynamicSharedMemorySize, GEMM_SMEM);
    cudaFuncSetAttribute(gemm_tc2<192,2>, cudaFuncAttributeMaxDynamicSharedMemorySize, GEMM_SMEM);
    cudaFuncSetAttribute(gemm_tc2<768,3>, cudaFuncAttributeMaxDynamicSharedMemorySize, GEMM_SMEM);

    // 0. pre-round weights to tf32
    round_w_kernel<<<(W_TOTAL + 255) / 256, 256>>>(qkv_w, proj_w, fc1_w, fc2_w, wr);

    // 1. LN1 + shift + window partition (rounded)
    ln_kernel<true><<<TOK / 8, 256>>>(x, norm1_w, norm1_b, hwin);

    // 2. QKV gemm
    gemm_tc2<192,0><<<dim3(9, TOK / 128), 128, GEMM_SMEM>>>(hwin, wr + W_QKV, qkv_b, nullptr, qkv, 576);

    // 3. attention (rounded output)
    attn_kernel<<<(TOK / NN) * HEADS, 128>>>(qkv, bias_table, rel_index, attn_mask, obuf);

    // 4. proj gemm + window-reverse scatter + residual(x) -> x1
    gemm_tc2<192,2><<<dim3(3, TOK / 128), 128, GEMM_SMEM>>>(obuf, wr + W_PROJ, proj_b, x, x1, CC);

    // 5. LN2 (rounded)
    ln_kernel<false><<<TOK / 8, 256>>>(x1, norm2_w, norm2_b, hwin);

    // 6. fc1 + gelu (rounded)
    gemm_tc2<192,1><<<dim3(12, TOK / 128), 128, GEMM_SMEM>>>(hwin, wr + W_FC1, fc1_b, nullptr, m1, HID);

    // 7. fc2 + residual -> out
    gemm_tc2<768,3><<<dim3(3, TOK / 128), 128, GEMM_SMEM>>>(m1, wr + W_FC2, fc2_b, x1, out, CC);
}